// round 1
// baseline (speedup 1.0000x reference)
#include <cuda_runtime.h>
#include <cstdint>

#define BATCH 256
#define QNUM 900
#define CNUM 91
#define QC (QNUM * CNUM)       // 81900
#define NV (QC / 4)            // 20475 float4 per row
#define K_SEL 100
#define CAP 4096
#define NTHREADS 512

// monotone float->uint mapping (order-preserving for all finite floats)
__device__ __forceinline__ uint32_t mono(float f) {
    uint32_t u = __float_as_uint(f);
    return u ^ ((u >> 31) ? 0xFFFFFFFFu : 0x80000000u);
}
__device__ __forceinline__ float unmono(uint32_t m) {
    uint32_t u = (m & 0x80000000u) ? (m ^ 0x80000000u) : ~m;
    return __uint_as_float(u);
}

__global__ __launch_bounds__(NTHREADS)
void postprocess_kernel(const float* __restrict__ logits,
                        const float* __restrict__ boxes_in,
                        const float* __restrict__ tsizes,
                        float* __restrict__ out)
{
    __shared__ unsigned long long cand[CAP];
    __shared__ int s_cnt;
    __shared__ uint32_t s_hist[256];
    __shared__ int s_digit, s_greater;
    __shared__ float bx0[K_SEL], by0[K_SEL], bx1[K_SEL], by1[K_SEL];
    __shared__ float barea[K_SEL], sscore[K_SEL];
    __shared__ unsigned char keepfl[K_SEL];

    const int b = blockIdx.x;
    const int tid = threadIdx.x;
    const float4* row = (const float4*)(logits + (size_t)b * QC);

    if (tid == 0) s_cnt = 0;
    __syncthreads();

    // ---- Pass 1: speculative candidate collection (threshold 2.5) ----
    const uint32_t SPEC = mono(2.5f);
    for (int i = tid; i < NV; i += NTHREADS) {
        float4 v = row[i];
        float vl[4] = {v.x, v.y, v.z, v.w};
        #pragma unroll
        for (int l = 0; l < 4; l++) {
            uint32_t m = mono(vl[l]);
            if (m >= SPEC) {
                int p = atomicAdd(&s_cnt, 1);
                if (p < CAP) {
                    uint32_t idx = (uint32_t)(i * 4 + l);
                    cand[p] = ((unsigned long long)m << 32) | (0xFFFFFFFFu - idx);
                }
            }
        }
    }
    __syncthreads();
    int n = s_cnt;

    // ---- Exact radix-select fallback (never taken for N(0,1) data) ----
    if (n < K_SEL || n > CAP) {
        uint32_t prefix = 0, pmask = 0;
        int need = K_SEL;
        for (int level = 3; level >= 0; level--) {
            for (int d = tid; d < 256; d += NTHREADS) s_hist[d] = 0;
            __syncthreads();
            for (int i = tid; i < NV; i += NTHREADS) {
                float4 v = row[i];
                float vl[4] = {v.x, v.y, v.z, v.w};
                #pragma unroll
                for (int l = 0; l < 4; l++) {
                    uint32_t m = mono(vl[l]);
                    if ((m & pmask) == prefix)
                        atomicAdd(&s_hist[(m >> (8 * level)) & 255u], 1u);
                }
            }
            __syncthreads();
            if (tid == 0) {
                int acc = 0, dsel = 0;
                for (int d = 255; d >= 0; d--) {
                    int h = (int)s_hist[d];
                    if (acc + h >= need) { dsel = d; break; }
                    acc += h;
                }
                s_digit = dsel;
                s_greater = acc;
            }
            __syncthreads();
            need -= s_greater;
            prefix |= ((uint32_t)s_digit) << (8 * level);
            pmask  |= 0xFFu << (8 * level);
            __syncthreads();
        }
        // prefix == exact 100th-largest key; collect all >= prefix
        if (tid == 0) s_cnt = 0;
        __syncthreads();
        for (int i = tid; i < NV; i += NTHREADS) {
            float4 v = row[i];
            float vl[4] = {v.x, v.y, v.z, v.w};
            #pragma unroll
            for (int l = 0; l < 4; l++) {
                uint32_t m = mono(vl[l]);
                if (m >= prefix) {
                    int p = atomicAdd(&s_cnt, 1);
                    if (p < CAP) {
                        uint32_t idx = (uint32_t)(i * 4 + l);
                        cand[p] = ((unsigned long long)m << 32) | (0xFFFFFFFFu - idx);
                    }
                }
            }
        }
        __syncthreads();
        n = min(s_cnt, CAP);
    }

    // ---- Bitonic sort descending (pad to pow2 with 0 = smallest key) ----
    int P = 128;
    while (P < n) P <<= 1;
    for (int i = n + tid; i < P; i += NTHREADS) cand[i] = 0ULL;
    __syncthreads();
    for (int k = 2; k <= P; k <<= 1) {
        for (int j = k >> 1; j > 0; j >>= 1) {
            for (int i = tid; i < P; i += NTHREADS) {
                int l = i ^ j;
                if (l > i) {
                    unsigned long long a = cand[i], c = cand[l];
                    bool descBlock = ((i & k) == 0);
                    bool doSwap = descBlock ? (a < c) : (a > c);
                    if (doSwap) { cand[i] = c; cand[l] = a; }
                }
            }
            __syncthreads();
        }
    }

    // ---- Top-100: scores, labels, boxes ----
    const int BK = BATCH * K_SEL;          // 25600
    if (tid < K_SEL) {
        unsigned long long e = cand[tid];
        uint32_t m = (uint32_t)(e >> 32);
        uint32_t idx = 0xFFFFFFFFu - (uint32_t)(e & 0xFFFFFFFFu);
        float logit = unmono(m);
        float score = 1.0f / (1.0f + expf(-logit));
        int q = idx / CNUM;
        int lab = idx - q * CNUM;
        const float* bp = boxes_in + ((size_t)b * QNUM + q) * 4;
        float cx = bp[0], cy = bp[1], w = bp[2], h = bp[3];
        float img_h = tsizes[2 * b], img_w = tsizes[2 * b + 1];
        float x0 = (cx - 0.5f * w) * img_w;
        float y0 = (cy - 0.5f * h) * img_h;
        float x1 = (cx + 0.5f * w) * img_w;
        float y1 = (cy + 0.5f * h) * img_h;
        bx0[tid] = x0; by0[tid] = y0; bx1[tid] = x1; by1[tid] = y1;
        barea[tid] = (x1 - x0) * (y1 - y0);
        sscore[tid] = score;
        keepfl[tid] = 1;

        int o = b * K_SEL + tid;
        out[o] = score;                       // scores
        out[BK + o] = (float)lab;             // labels
        float* ob = out + 2 * BK + (size_t)o * 4;
        ob[0] = x0; ob[1] = y0; ob[2] = x1; ob[3] = y1;   // boxes
    }
    __syncthreads();

    // ---- Greedy NMS (sequential over i, parallel over j) ----
    for (int i = 0; i < K_SEL - 1; i++) {
        bool ki = (keepfl[i] != 0);
        if (ki && tid > i && tid < K_SEL && keepfl[tid]) {
            float lx = fmaxf(bx0[i], bx0[tid]);
            float ly = fmaxf(by0[i], by0[tid]);
            float rx = fminf(bx1[i], bx1[tid]);
            float ry = fminf(by1[i], by1[tid]);
            float iw = fmaxf(rx - lx, 0.0f);
            float ih = fmaxf(ry - ly, 0.0f);
            float inter = iw * ih;
            float uni = barea[i] + barea[tid] - inter;
            float iou = inter / fmaxf(uni, 1e-9f);
            if (iou > 0.7f) keepfl[tid] = 0;
        }
        __syncthreads();
    }
    if (tid < K_SEL) {
        int o = b * K_SEL + tid;
        out[6 * BK + o] = (sscore[tid] > 0.3f && keepfl[tid]) ? 1.0f : 0.0f;
    }
}

extern "C" void kernel_launch(void* const* d_in, const int* in_sizes, int n_in,
                              void* d_out, int out_size)
{
    const float* logits   = (const float*)d_in[0];   // (256, 900, 91) f32
    const float* boxes_in = (const float*)d_in[1];   // (256, 900, 4)  f32
    const float* tsizes   = (const float*)d_in[2];   // (256, 2)       f32
    float* out = (float*)d_out;
    postprocess_kernel<<<BATCH, NTHREADS>>>(logits, boxes_in, tsizes, out);
}